// round 6
// baseline (speedup 1.0000x reference)
#include <cuda_runtime.h>
#include <cuda_fp16.h>
#include <cstdint>
#include <cstddef>
#include <math.h>

#define NB  16
#define NLQ 1024
#define NLK 1024
#define NDK 256
#define NDV 256

__device__ float    g_ks[NB * NLK];
__device__ unsigned g_maxi[NB];
__device__ float    g_es[NB * NLK];                // exp(ks - mx)*2^64, fp32
__device__ float    g_inv[NB * NLQ];               // 1 / rowmax(masked es)
__device__ unsigned g_bits[NB * NLQ * 32];         // packed mask bits, 2 MB
__device__ __half   g_vt[(size_t)NB * NDV * NLK];  // fp16 V^T [b][dv][k]

__device__ __forceinline__ unsigned enc_ord(float f) {
    int x = __float_as_int(f);
    return (x >= 0) ? ((unsigned)x | 0x80000000u) : ~(unsigned)x;
}
__device__ __forceinline__ float dec_ord(unsigned u) {
    int x = (u & 0x80000000u) ? (int)(u & 0x7fffffffu) : (int)~u;
    return __int_as_float(x);
}

__global__ void init_kernel() { if (threadIdx.x < NB) g_maxi[threadIdx.x] = 0u; }

// ---- k_s = key·w, per-batch max --------------------------------------------
__global__ void ks_kernel(const float* __restrict__ key, const float* __restrict__ w) {
    __shared__ float ws[NDK];
    __shared__ float bm[8];
    int t = threadIdx.x;
    ws[t] = w[t];
    __syncthreads();
    int warp = t >> 5, lane = t & 31;
    int row = blockIdx.x * 8 + warp;
    const float4* kp = (const float4*)(key + (size_t)row * NDK);
    const float4* wp = (const float4*)ws;
    float s = 0.f;
#pragma unroll
    for (int i = 0; i < 2; i++) {
        float4 a = kp[lane + 32 * i], b4 = wp[lane + 32 * i];
        s = fmaf(a.x, b4.x, s); s = fmaf(a.y, b4.y, s);
        s = fmaf(a.z, b4.z, s); s = fmaf(a.w, b4.w, s);
    }
#pragma unroll
    for (int o = 16; o; o >>= 1) s += __shfl_xor_sync(0xffffffffu, s, o);
    if (lane == 0) { g_ks[row] = s; bm[warp] = s; }
    __syncthreads();
    if (t == 0) {
        float m = bm[0];
#pragma unroll
        for (int i = 1; i < 8; i++) m = fmaxf(m, bm[i]);
        atomicMax(&g_maxi[(unsigned)blockIdx.x >> 7], enc_ord(m));
    }
}

// ---- es = exp(ks - mx + 64 ln2), fp32 --------------------------------------
__global__ void escale_kernel() {
    int b = blockIdx.x, t = threadIdx.x;
    float mx = dec_ord(g_maxi[b]);
    g_es[b * NLK + t] = expf(g_ks[b * NLK + t] - mx + 44.3614195558365f);
}

// ---- per-row masked max (exact) + mask bit-pack ----------------------------
__global__ void rowmax_kernel(const int* __restrict__ mask) {
    int wid = threadIdx.x >> 5, lane = threadIdx.x & 31;
    int row = blockIdx.x * 8 + wid;             // 2048 blocks x 8 rows
    int b = row >> 10;
    const int4*   mp = (const int4*)(mask + (size_t)row * NLK + lane * 32);
    const float4* ep = (const float4*)(g_es + b * NLK + lane * 32);
    float m = 0.f;
    unsigned w = 0;
#pragma unroll
    for (int i = 0; i < 8; i++) {
        int4 mm = mp[i];
        float4 ee = ep[i];
        if (mm.x) m = fmaxf(m, ee.x);
        if (mm.y) m = fmaxf(m, ee.y);
        if (mm.z) m = fmaxf(m, ee.z);
        if (mm.w) m = fmaxf(m, ee.w);
        w |= ((unsigned)(mm.x & 1) << (4 * i))
           | ((unsigned)(mm.y & 1) << (4 * i + 1))
           | ((unsigned)(mm.z & 1) << (4 * i + 2))
           | ((unsigned)(mm.w & 1) << (4 * i + 3));
    }
    g_bits[row * 32 + lane] = w;
#pragma unroll
    for (int o = 16; o; o >>= 1) m = fmaxf(m, __shfl_xor_sync(0xffffffffu, m, o));
    if (lane == 0) g_inv[row] = 1.0f / m;
}

// ---- V^T fp16 transpose ----------------------------------------------------
__global__ void vt_kernel(const float* __restrict__ value) {
    __shared__ float tile[32][33];
    int b = blockIdx.z, k0 = blockIdx.y * 32, dv0 = blockIdx.x * 32;
    int t = threadIdx.x;
    int r = t >> 3, c4 = (t & 7) * 4;
    float4 v = *(const float4*)(value + ((size_t)(b * NLK + k0 + r)) * NDV + dv0 + c4);
    tile[r][c4 + 0] = v.x; tile[r][c4 + 1] = v.y;
    tile[r][c4 + 2] = v.z; tile[r][c4 + 3] = v.w;
    __syncthreads();
    __half2 h0 = __floats2half2_rn(tile[c4 + 0][r], tile[c4 + 1][r]);
    __half2 h1 = __floats2half2_rn(tile[c4 + 2][r], tile[c4 + 3][r]);
    uint2 o;
    o.x = *(unsigned*)&h0; o.y = *(unsigned*)&h1;
    *(uint2*)(g_vt + ((size_t)(b * NDV + dv0 + r)) * NLK + k0 + c4) = o;
}

// ---- fp16 GEMM, per-row scaled A -------------------------------------------
#define BM 128
#define BN 256
#define BK 32
#define STG 3
#define APITCH 80
#define BPITCH 80
#define A_STAGE (BM * APITCH)
#define B_STAGE (BN * BPITCH)
#define OFF_B   (STG * A_STAGE)            // 30720
#define OFF_ES  (OFF_B + STG * B_STAGE)    // 92160 (4 KB)
#define OFF_D   (OFF_ES + 4096)            // 96256 (2 KB)
#define SMEM_REQ (OFF_D + 2048)            // 98304

__global__ __launch_bounds__(512, 1)
void attn_gemm(const int* __restrict__ mask, float* __restrict__ out) {
    extern __shared__ char smem[];
    const uint32_t sm = (uint32_t)__cvta_generic_to_shared(smem);
    float* Dens = (float*)(smem + OFF_D);

    const int tid = threadIdx.x, lane = tid & 31, wid = tid >> 5;
    const int b = blockIdx.y, qbase = blockIdx.x * BM;
    const int warpM = wid >> 3, warpN = wid & 7;
    const int g = lane >> 2, t4 = lane & 3;

    // es table to smem (fp32, 4 KB)
    {
        float2 e2 = ((const float2*)(g_es + b * NLK))[tid];
        ((float2*)(smem + OFF_ES))[tid] = e2;
    }
    __syncthreads();

    const int ar = tid & 127, aq = tid >> 7;
    const int grow = b * NLQ + qbase + ar;
    const float inv = g_inv[grow];
    const unsigned* brow = g_bits + (size_t)grow * 32;
    const int n0 = tid >> 1, cc0 = (tid & 1) * 2;
    const __half* vb0 = g_vt + ((size_t)(b * NDV + n0)) * NLK + cc0 * 8;
    const uint32_t bd0 = sm + OFF_B + (uint32_t)(n0 * BPITCH + cc0 * 16);

    float c[4][4][4];
#pragma unroll
    for (int i = 0; i < 4; i++)
#pragma unroll
        for (int j = 0; j < 4; j++)
#pragma unroll
            for (int k = 0; k < 4; k++) c[i][j][k] = 0.f;
    float dacc = 0.f;

    auto cpB = [&](int t, int s) {
        uint32_t dst = bd0 + (uint32_t)(s * B_STAGE);
        const __half* src = vb0 + t * BK;
        asm volatile("cp.async.cg.shared.global [%0], [%1], 16;" :: "r"(dst), "l"(src));
        asm volatile("cp.async.cg.shared.global [%0], [%1], 16;" :: "r"(dst + 16), "l"(src + 8));
        asm volatile("cp.async.commit_group;" ::: "memory");
    };
    auto stsA = [&](int t, int s, unsigned bw) {
        unsigned u = (bw >> (aq * 8)) & 0xFFu;
        float4 e0, e1;
        uint32_t ea = sm + OFF_ES + (uint32_t)(t * 128 + aq * 32);
        asm volatile("ld.shared.v4.f32 {%0,%1,%2,%3}, [%4];"
                     : "=f"(e0.x), "=f"(e0.y), "=f"(e0.z), "=f"(e0.w) : "r"(ea));
        asm volatile("ld.shared.v4.f32 {%0,%1,%2,%3}, [%4];"
                     : "=f"(e1.x), "=f"(e1.y), "=f"(e1.z), "=f"(e1.w) : "r"(ea + 16));
        float a0 = (u & 1u)   ? e0.x * inv : 0.f;
        float a1 = (u & 2u)   ? e0.y * inv : 0.f;
        float a2 = (u & 4u)   ? e0.z * inv : 0.f;
        float a3 = (u & 8u)   ? e0.w * inv : 0.f;
        float a4 = (u & 16u)  ? e1.x * inv : 0.f;
        float a5 = (u & 32u)  ? e1.y * inv : 0.f;
        float a6 = (u & 64u)  ? e1.z * inv : 0.f;
        float a7 = (u & 128u) ? e1.w * inv : 0.f;
        __half2 h0 = __floats2half2_rn(a0, a1);
        __half2 h1 = __floats2half2_rn(a2, a3);
        __half2 h2 = __floats2half2_rn(a4, a5);
        __half2 h3 = __floats2half2_rn(a6, a7);
        float2 f0 = __half22float2(h0), f1 = __half22float2(h1);
        float2 f2 = __half22float2(h2), f3 = __half22float2(h3);
        dacc += (f0.x + f0.y) + (f1.x + f1.y) + (f2.x + f2.y) + (f3.x + f3.y);
        asm volatile("st.shared.v4.b32 [%0], {%1,%2,%3,%4};"
                     :: "r"(sm + (uint32_t)(s * A_STAGE + ar * APITCH + aq * 16)),
                        "r"(*(unsigned*)&h0), "r"(*(unsigned*)&h1),
                        "r"(*(unsigned*)&h2), "r"(*(unsigned*)&h3));
    };
    auto compute = [&](int s) {
        const uint32_t Ab = sm + (uint32_t)(s * A_STAGE);
        const uint32_t Bb = sm + OFF_B + (uint32_t)(s * B_STAGE);
#pragma unroll
        for (int k16 = 0; k16 < 2; k16++) {
            uint32_t a[4][4], bq[4][2];
#pragma unroll
            for (int mt = 0; mt < 4; mt++) {
                uint32_t base = Ab + (uint32_t)((warpM * 64 + mt * 16 + g) * APITCH
                                                + k16 * 32 + t4 * 4);
                asm volatile("ld.shared.b32 %0, [%1];" : "=r"(a[mt][0]) : "r"(base));
                asm volatile("ld.shared.b32 %0, [%1];" : "=r"(a[mt][1]) : "r"(base + 8 * APITCH));
                asm volatile("ld.shared.b32 %0, [%1];" : "=r"(a[mt][2]) : "r"(base + 16));
                asm volatile("ld.shared.b32 %0, [%1];" : "=r"(a[mt][3]) : "r"(base + 8 * APITCH + 16));
            }
#pragma unroll
            for (int nt = 0; nt < 4; nt++) {
                uint32_t base = Bb + (uint32_t)((warpN * 32 + nt * 8 + g) * BPITCH
                                                + k16 * 32 + t4 * 4);
                asm volatile("ld.shared.b32 %0, [%1];" : "=r"(bq[nt][0]) : "r"(base));
                asm volatile("ld.shared.b32 %0, [%1];" : "=r"(bq[nt][1]) : "r"(base + 16));
            }
#pragma unroll
            for (int mt = 0; mt < 4; mt++)
#pragma unroll
                for (int nt = 0; nt < 4; nt++)
                    asm volatile(
                        "mma.sync.aligned.m16n8k16.row.col.f32.f16.f16.f32 "
                        "{%0,%1,%2,%3}, {%4,%5,%6,%7}, {%8,%9}, {%0,%1,%2,%3};"
                        : "+f"(c[mt][nt][0]), "+f"(c[mt][nt][1]),
                          "+f"(c[mt][nt][2]), "+f"(c[mt][nt][3])
                        : "r"(a[mt][0]), "r"(a[mt][1]), "r"(a[mt][2]), "r"(a[mt][3]),
                          "r"(bq[nt][0]), "r"(bq[nt][1]));
        }
    };

    // ---- 3-stage pipeline ----
    unsigned bw = brow[0], bw_next;
    cpB(0, 0);
    cpB(1, 1);
    const int NKT = NLK / BK;   // 32
    for (int t = 0; t < NKT; t++) {
        int cs = t % 3;
        stsA(t, cs, bw);
        if (t + 1 < NKT) bw_next = brow[t + 1];
        if (t + 1 < NKT) asm volatile("cp.async.wait_group 1;" ::: "memory");
        else             asm volatile("cp.async.wait_group 0;" ::: "memory");
        __syncthreads();
        if (t + 2 < NKT) cpB(t + 2, (t + 2) % 3);
        compute(cs);
        bw = bw_next;
    }

    // ---- denominators & epilogue ----
    Dens[ar * 4 + aq] = dacc;
    __syncthreads();
#pragma unroll
    for (int mt = 0; mt < 4; mt++) {
        const int row = warpM * 64 + mt * 16 + g;
        float4 d0 = *(const float4*)(Dens + row * 4);
        float4 d1 = *(const float4*)(Dens + (row + 8) * 4);
        float inv0 = 1.0f / (d0.x + d0.y + d0.z + d0.w);
        float inv8 = 1.0f / (d1.x + d1.y + d1.z + d1.w);
        float* o0 = out + ((size_t)(b * NLQ + qbase + row)) * NDV;
#pragma unroll
        for (int nt = 0; nt < 4; nt++) {
            const int col = warpN * 32 + nt * 8 + 2 * t4;
            *(float2*)(o0 + col) =
                make_float2(c[mt][nt][0] * inv0, c[mt][nt][1] * inv0);
            *(float2*)(o0 + 8 * NDV + col) =
                make_float2(c[mt][nt][2] * inv8, c[mt][nt][3] * inv8);
        }
    }
}

// ---------------- launcher --------------------------------------------------
extern "C" void kernel_launch(void* const* d_in, const int* in_sizes, int n_in,
                              void* d_out, int out_size) {
    const float* key   = (const float*)d_in[1];
    const float* value = (const float*)d_in[2];
    const float* w     = (const float*)d_in[3];
    const int*   mask  = (const int*)d_in[4];
    float*       out   = (float*)d_out;

    cudaFuncSetAttribute(attn_gemm,
                         cudaFuncAttributeMaxDynamicSharedMemorySize, SMEM_REQ);

    init_kernel<<<1, 32>>>();
    ks_kernel<<<NB * NLK / 8, 256>>>(key, w);
    escale_kernel<<<NB, 1024>>>();
    rowmax_kernel<<<NB * NLQ / 8, 256>>>(mask);
    dim3 vg(NDV / 32, NLK / 32, NB);
    vt_kernel<<<vg, 256>>>(value);
    dim3 grid(NLQ / BM, NB);
    attn_gemm<<<grid, 512, SMEM_REQ>>>(mask, out);
}

// round 9
// speedup vs baseline: 1.4734x; 1.4734x over previous
#include <cuda_runtime.h>
#include <cuda_fp16.h>
#include <cstdint>
#include <cstddef>
#include <math.h>

#define NB  16
#define NLQ 1024
#define NLK 1024
#define NDK 256
#define NDV 256

__device__ float    g_ks[NB * NLK];
__device__ unsigned g_maxi[NB];                    // zero-init; atomicMax idempotent
__device__ float    g_es[NB * NLK];
__device__ float    g_inv[NB * NLQ];
__device__ unsigned g_bits[NB * NLQ * 32];         // permuted: word w bit 4i+c <-> k=i*128+w*4+c
__device__ __half   g_vt[(size_t)NB * NDV * NLK];

__device__ __forceinline__ unsigned enc_ord(float f) {
    int x = __float_as_int(f);
    return (x >= 0) ? ((unsigned)x | 0x80000000u) : ~(unsigned)x;
}
__device__ __forceinline__ float dec_ord(unsigned u) {
    int x = (u & 0x80000000u) ? (int)(u & 0x7fffffffu) : (int)~u;
    return __int_as_float(x);
}

// ---- k_s = key·w, per-batch max --------------------------------------------
__global__ void ks_kernel(const float* __restrict__ key, const float* __restrict__ w) {
    __shared__ float ws[NDK];
    __shared__ float bm[8];
    int t = threadIdx.x;
    ws[t] = w[t];
    __syncthreads();
    int warp = t >> 5, lane = t & 31;
    int row = blockIdx.x * 8 + warp;
    const float4* kp = (const float4*)(key + (size_t)row * NDK);
    const float4* wp = (const float4*)ws;
    float s = 0.f;
#pragma unroll
    for (int i = 0; i < 2; i++) {
        float4 a = kp[lane + 32 * i], b4 = wp[lane + 32 * i];
        s = fmaf(a.x, b4.x, s); s = fmaf(a.y, b4.y, s);
        s = fmaf(a.z, b4.z, s); s = fmaf(a.w, b4.w, s);
    }
#pragma unroll
    for (int o = 16; o; o >>= 1) s += __shfl_xor_sync(0xffffffffu, s, o);
    if (lane == 0) { g_ks[row] = s; bm[warp] = s; }
    __syncthreads();
    if (t == 0) {
        float m = bm[0];
#pragma unroll
        for (int i = 1; i < 8; i++) m = fmaxf(m, bm[i]);
        atomicMax(&g_maxi[(unsigned)blockIdx.x >> 7], enc_ord(m));
    }
}

// ---- es = exp(ks - mx + 64 ln2), fp32 --------------------------------------
__global__ void escale_kernel() {
    int b = blockIdx.x, t = threadIdx.x;
    float mx = dec_ord(g_maxi[b]);
    g_es[b * NLK + t] = expf(g_ks[b * NLK + t] - mx + 44.3614195558365f);
}

// ---- per-row masked max + bit-pack (COALESCED, permuted layout) ------------
__global__ void rowmax_kernel(const int* __restrict__ mask) {
    int wid = threadIdx.x >> 5, lane = threadIdx.x & 31;
    int row = blockIdx.x * 8 + wid;
    int b = row >> 10;
    const int4*   mp = (const int4*)(mask + (size_t)row * NLK);
    const float4* ep = (const float4*)(g_es + b * NLK);
    float m = 0.f;
    unsigned w = 0;
#pragma unroll
    for (int i = 0; i < 8; i++) {
        int idx = i * 32 + lane;            // k = idx*4 = i*128 + lane*4 (coalesced)
        int4 mm = mp[idx];
        float4 ee = ep[idx];
        if (mm.x) m = fmaxf(m, ee.x);
        if (mm.y) m = fmaxf(m, ee.y);
        if (mm.z) m = fmaxf(m, ee.z);
        if (mm.w) m = fmaxf(m, ee.w);
        unsigned nib = (unsigned)(mm.x & 1) | ((unsigned)(mm.y & 1) << 1)
                     | ((unsigned)(mm.z & 1) << 2) | ((unsigned)(mm.w & 1) << 3);
        w |= nib << (4 * i);
    }
    g_bits[row * 32 + lane] = w;
#pragma unroll
    for (int o = 16; o; o >>= 1) m = fmaxf(m, __shfl_xor_sync(0xffffffffu, m, o));
    if (lane == 0) g_inv[row] = 1.0f / m;
}

// ---- V^T fp16 transpose ----------------------------------------------------
__global__ void vt_kernel(const float* __restrict__ value) {
    __shared__ float tile[32][33];
    int b = blockIdx.z, k0 = blockIdx.y * 32, dv0 = blockIdx.x * 32;
    int t = threadIdx.x;
    int r = t >> 3, c4 = (t & 7) * 4;
    float4 v = *(const float4*)(value + ((size_t)(b * NLK + k0 + r)) * NDV + dv0 + c4);
    tile[r][c4 + 0] = v.x; tile[r][c4 + 1] = v.y;
    tile[r][c4 + 2] = v.z; tile[r][c4 + 3] = v.w;
    __syncthreads();
    __half2 h0 = __floats2half2_rn(tile[c4 + 0][r], tile[c4 + 1][r]);
    __half2 h1 = __floats2half2_rn(tile[c4 + 2][r], tile[c4 + 3][r]);
    uint2 o;
    o.x = *(unsigned*)&h0; o.y = *(unsigned*)&h1;
    *(uint2*)(g_vt + ((size_t)(b * NDV + dv0 + r)) * NLK + k0 + c4) = o;
}

// ---- fp16 GEMM, ldmatrix operands, per-row scaled A ------------------------
#define BM 128
#define BN 256
#define BK 32
#define STG 3
#define APITCH 80
#define BPITCH 80
#define A_STAGE (BM * APITCH)
#define B_STAGE (BN * BPITCH)
#define OFF_B   (STG * A_STAGE)
#define OFF_ES  (OFF_B + STG * B_STAGE)
#define OFF_D   (OFF_ES + 4096)
#define SMEM_REQ (OFF_D + 2048)

__device__ __forceinline__ void ldsm4(uint32_t* r, uint32_t addr) {
    asm volatile("ldmatrix.sync.aligned.m8n8.x4.shared.b16 {%0,%1,%2,%3}, [%4];"
                 : "=r"(r[0]), "=r"(r[1]), "=r"(r[2]), "=r"(r[3]) : "r"(addr));
}

__global__ __launch_bounds__(512, 1)
void attn_gemm(float* __restrict__ out) {
    extern __shared__ char smem[];
    const uint32_t sm = (uint32_t)__cvta_generic_to_shared(smem);
    float* Dens = (float*)(smem + OFF_D);

    const int tid = threadIdx.x, lane = tid & 31, wid = tid >> 5;
    const int b = blockIdx.y, qbase = blockIdx.x * BM;
    const int warpM = wid >> 3, warpN = wid & 7;
    const int g = lane >> 2, t4 = lane & 3;

    {
        float2 e2 = ((const float2*)(g_es + b * NLK))[tid];
        ((float2*)(smem + OFF_ES))[tid] = e2;
    }
    __syncthreads();

    const int ar = tid & 127, aq = tid >> 7;       // row, k-eighth (8 k each)
    const int grow = b * NLQ + qbase + ar;
    const float inv = g_inv[grow];
    // preload the 8 bit-words this thread ever needs (permuted layout)
    unsigned bwreg[8];
    {
        const uint2* bp = (const uint2*)(g_bits + (size_t)grow * 32);
#pragma unroll
        for (int j = 0; j < 4; j++) {
            uint2 v = bp[aq + 4 * j];              // words 2aq+8j, 2aq+8j+1
            bwreg[2 * j] = v.x; bwreg[2 * j + 1] = v.y;
        }
    }
    const int n0 = tid >> 1, cc0 = (tid & 1) * 2;
    const __half* vb0 = g_vt + ((size_t)(b * NDV + n0)) * NLK + cc0 * 8;
    const uint32_t bd0 = sm + OFF_B + (uint32_t)(n0 * BPITCH + cc0 * 16);

    float c[4][4][4];
#pragma unroll
    for (int i = 0; i < 4; i++)
#pragma unroll
        for (int j = 0; j < 4; j++)
#pragma unroll
            for (int k = 0; k < 4; k++) c[i][j][k] = 0.f;
    float dacc = 0.f;

    auto cpB = [&](int t, int s) {
        uint32_t dst = bd0 + (uint32_t)(s * B_STAGE);
        const __half* src = vb0 + t * BK;
        asm volatile("cp.async.cg.shared.global [%0], [%1], 16;" :: "r"(dst), "l"(src));
        asm volatile("cp.async.cg.shared.global [%0], [%1], 16;" :: "r"(dst + 16), "l"(src + 8));
        asm volatile("cp.async.commit_group;" ::: "memory");
    };
    auto stsA = [&](int t, int s) {
        const int j = t & 3, i4 = (t >> 2) * 4;
        unsigned u = ((bwreg[2 * j] >> i4) & 0xFu) | (((bwreg[2 * j + 1] >> i4) & 0xFu) << 4);
        float4 e0, e1;
        uint32_t ea = sm + OFF_ES + (uint32_t)(t * 128 + aq * 32);
        asm volatile("ld.shared.v4.f32 {%0,%1,%2,%3}, [%4];"
                     : "=f"(e0.x), "=f"(e0.y), "=f"(e0.z), "=f"(e0.w) : "r"(ea));
        asm volatile("ld.shared.v4.f32 {%0,%1,%2,%3}, [%4];"
                     : "=f"(e1.x), "=f"(e1.y), "=f"(e1.z), "=f"(e1.w) : "r"(ea + 16));
        float a0 = (u & 1u)   ? e0.x * inv : 0.f;
        float a1 = (u & 2u)   ? e0.y * inv : 0.f;
        float a2 = (u & 4u)   ? e0.z * inv : 0.f;
        float a3 = (u & 8u)   ? e0.w * inv : 0.f;
        float a4 = (u & 16u)  ? e1.x * inv : 0.f;
        float a5 = (u & 32u)  ? e1.y * inv : 0.f;
        float a6 = (u & 64u)  ? e1.z * inv : 0.f;
        float a7 = (u & 128u) ? e1.w * inv : 0.f;
        __half2 h0 = __floats2half2_rn(a0, a1);
        __half2 h1 = __floats2half2_rn(a2, a3);
        __half2 h2 = __floats2half2_rn(a4, a5);
        __half2 h3 = __floats2half2_rn(a6, a7);
        float2 f0 = __half22float2(h0), f1 = __half22float2(h1);
        float2 f2 = __half22float2(h2), f3 = __half22float2(h3);
        dacc += (f0.x + f0.y) + (f1.x + f1.y) + (f2.x + f2.y) + (f3.x + f3.y);
        asm volatile("st.shared.v4.b32 [%0], {%1,%2,%3,%4};"
                     :: "r"(sm + (uint32_t)(s * A_STAGE + ar * APITCH + aq * 16)),
                        "r"(*(unsigned*)&h0), "r"(*(unsigned*)&h1),
                        "r"(*(unsigned*)&h2), "r"(*(unsigned*)&h3));
    };
    auto compute = [&](int s) {
        const uint32_t Ab = sm + (uint32_t)(s * A_STAGE);
        const uint32_t Bb = sm + OFF_B + (uint32_t)(s * B_STAGE);
        const uint32_t aad = Ab + (uint32_t)((warpM * 64 + (lane & 15)) * APITCH
                                             + (lane >> 4) * 16);
        const uint32_t bad = Bb + (uint32_t)((warpN * 32 + (lane & 7) + (lane >> 4) * 8) * BPITCH
                                             + ((lane >> 3) & 1) * 16);
#pragma unroll
        for (int k16 = 0; k16 < 2; k16++) {
            uint32_t a[4][4], bq[2][4];
#pragma unroll
            for (int mt = 0; mt < 4; mt++)
                ldsm4(a[mt], aad + (uint32_t)(mt * 16 * APITCH + k16 * 32));
#pragma unroll
            for (int np = 0; np < 2; np++)
                ldsm4(bq[np], bad + (uint32_t)(np * 16 * BPITCH + k16 * 32));
#pragma unroll
            for (int mt = 0; mt < 4; mt++)
#pragma unroll
                for (int nt = 0; nt < 4; nt++) {
                    const uint32_t b0 = bq[nt >> 1][(nt & 1) * 2];
                    const uint32_t b1 = bq[nt >> 1][(nt & 1) * 2 + 1];
                    asm volatile(
                        "mma.sync.aligned.m16n8k16.row.col.f32.f16.f16.f32 "
                        "{%0,%1,%2,%3}, {%4,%5,%6,%7}, {%8,%9}, {%0,%1,%2,%3};"
                        : "+f"(c[mt][nt][0]), "+f"(c[mt][nt][1]),
                          "+f"(c[mt][nt][2]), "+f"(c[mt][nt][3])
                        : "r"(a[mt][0]), "r"(a[mt][1]), "r"(a[mt][2]), "r"(a[mt][3]),
                          "r"(b0), "r"(b1));
                }
        }
    };

    // ---- 3-stage pipeline ----
    cpB(0, 0);
    cpB(1, 1);
    const int NKT = NLK / BK;   // 32
    for (int t = 0; t < NKT; t++) {
        int cs = t % 3;
        stsA(t, cs);
        if (t + 1 < NKT) asm volatile("cp.async.wait_group 1;" ::: "memory");
        else             asm volatile("cp.async.wait_group 0;" ::: "memory");
        __syncthreads();
        if (t + 2 < NKT) cpB(t + 2, (t + 2) % 3);
        compute(cs);
    }

    // ---- denominators & epilogue ----
    Dens[ar * 4 + aq] = dacc;
    __syncthreads();
#pragma unroll
    for (int mt = 0; mt < 4; mt++) {
        const int row = warpM * 64 + mt * 16 + g;
        float4 d0 = *(const float4*)(Dens + row * 4);
        float4 d1 = *(const float4*)(Dens + (row + 8) * 4);
        float inv0 = 1.0f / (d0.x + d0.y + d0.z + d0.w);
        float inv8 = 1.0f / (d1.x + d1.y + d1.z + d1.w);
        float* o0 = out + ((size_t)(b * NLQ + qbase + row)) * NDV;
#pragma unroll
        for (int nt = 0; nt < 4; nt++) {
            const int col = warpN * 32 + nt * 8 + 2 * t4;
            *(float2*)(o0 + col) =
                make_float2(c[mt][nt][0] * inv0, c[mt][nt][1] * inv0);
            *(float2*)(o0 + 8 * NDV + col) =
                make_float2(c[mt][nt][2] * inv8, c[mt][nt][3] * inv8);
        }
    }
}

// ---------------- launcher --------------------------------------------------
extern "C" void kernel_launch(void* const* d_in, const int* in_sizes, int n_in,
                              void* d_out, int out_size) {
    const float* key   = (const float*)d_in[1];
    const float* value = (const float*)d_in[2];
    const float* w     = (const float*)d_in[3];
    const int*   mask  = (const int*)d_in[4];
    float*       out   = (float*)d_out;

    cudaFuncSetAttribute(attn_gemm,
                         cudaFuncAttributeMaxDynamicSharedMemorySize, SMEM_REQ);

    ks_kernel<<<NB * NLK / 8, 256>>>(key, w);
    escale_kernel<<<NB, 1024>>>();
    rowmax_kernel<<<NB * NLQ / 8, 256>>>(mask);
    dim3 vg(NDV / 32, NLK / 32, NB);
    vt_kernel<<<vg, 256>>>(value);
    dim3 grid(NLQ / BM, NB);
    attn_gemm<<<grid, 512, SMEM_REQ>>>(out);
}